// round 17
// baseline (speedup 1.0000x reference)
#include <cuda_runtime.h>
#include <cstdint>

// ============================================================
// Linear y = x@W + b, x:[262144,128] f32, W:[128,128] f32, b:[128] f32.
// mma.sync m16n8k8 tf32, 2 CTAs x 128 thr, warp tile 64x32, B (W^T tf32)
// fully in registers, 3-stage cp.async pipeline, B loaded in-kernel from W
// (= R16, best known: 57.1us).
// R17 = R16 + ONE change: epilogue stores use st.global.cs (evict-first
// streaming) so the 128MB write-once output stream does not churn L2 and
// evict the x read stream.
// ============================================================

#define BATCH    262144
#define NF       128
#define TILE_M   64
#define NTILES   (BATCH / TILE_M)   // 4096
#define GRID     296                // 2 CTAs x 148 SMs
#define THREADS  128                // 4 warps: 1 (M) x 4 (N)
#define NBUF     3

#define SM_BUF_BYTES 32768          // one A tile (64 rows x 512B)
#define SM_TOTAL     (NBUF * SM_BUF_BYTES)

__device__ __forceinline__ uint32_t smem_u32(const void* p) {
    uint32_t a;
    asm("{ .reg .u64 t; cvta.to.shared.u64 t, %1; cvt.u32.u64 %0, t; }" : "=r"(a) : "l"(p));
    return a;
}

__device__ __forceinline__ float tf32_rna(float v) {
    uint32_t t;
    asm("cvt.rna.tf32.f32 %0, %1;" : "=r"(t) : "f"(v));
    return __uint_as_float(t);
}

__device__ __forceinline__ void ldm4(uint32_t& r0, uint32_t& r1, uint32_t& r2, uint32_t& r3,
                                     uint32_t addr) {
    asm volatile("ldmatrix.sync.aligned.m8n8.x4.shared.b16 {%0,%1,%2,%3}, [%4];"
                 : "=r"(r0), "=r"(r1), "=r"(r2), "=r"(r3) : "r"(addr));
}

__device__ __forceinline__ void mma_tf32(float& c0, float& c1, float& c2, float& c3,
                                         uint32_t a0, uint32_t a1, uint32_t a2, uint32_t a3,
                                         float bf0, float bf1) {
    uint32_t b0 = __float_as_uint(bf0), b1 = __float_as_uint(bf1);
    asm volatile(
        "mma.sync.aligned.m16n8k8.row.col.f32.tf32.tf32.f32 "
        "{%0,%1,%2,%3}, {%4,%5,%6,%7}, {%8,%9}, {%0,%1,%2,%3};"
        : "+f"(c0), "+f"(c1), "+f"(c2), "+f"(c3)
        : "r"(a0), "r"(a1), "r"(a2), "r"(a3), "r"(b0), "r"(b1));
}

// streaming (evict-first) 8-byte store
__device__ __forceinline__ void stg_cs_v2(float* p, float vx, float vy) {
    asm volatile("st.global.cs.v2.f32 [%0], {%1, %2};" :: "l"(p), "f"(vx), "f"(vy) : "memory");
}

// Load one 64x128 f32 A tile into smem with per-8-row 16B-chunk XOR swizzle:
// phys(row, chunk) = row*512 + ((chunk ^ (row&7)) << 4), chunk = 0..31.
__device__ __forceinline__ void load_tile(uint32_t sdst, const float* __restrict__ gx, int tid) {
    #pragma unroll
    for (int i = 0; i < 16; i++) {
        int id  = tid + i * THREADS;          // 0..2047
        int row = id >> 5;                    // 0..63
        int c   = id & 31;
        uint32_t dst = sdst + row * 512 + ((c ^ (row & 7)) << 4);
        const float* src = gx + row * NF + c * 4;
        asm volatile("cp.async.cg.shared.global [%0], [%1], 16;" :: "r"(dst), "l"(src) : "memory");
    }
}

__global__ __launch_bounds__(THREADS, 2) void gemm_kernel(const float* __restrict__ x,
                                                          const float* __restrict__ W,
                                                          const float* __restrict__ bias,
                                                          float* __restrict__ out) {
    extern __shared__ char smem[];
    const uint32_t sbase = smem_u32(smem);
    const int tid  = threadIdx.x;
    const int lane = tid & 31;
    const int nc   = tid >> 5;      // warp id = N column (0..3)
    const int g    = lane >> 2;     // groupID (row within 8)
    const int tig  = lane & 3;      // threadID_in_group

    const int t0 = blockIdx.x;

    // prologue: prefetch 2 tiles first so the one-time B load overlaps the
    // initial DRAM latency (t0, t0+GRID always < NTILES since t0 < 296)
    load_tile(sbase + 0 * SM_BUF_BYTES, x + (size_t)t0 * TILE_M * NF, tid);
    asm volatile("cp.async.commit_group;" ::: "memory");
    load_tile(sbase + 1 * SM_BUF_BYTES, x + (size_t)(t0 + GRID) * TILE_M * NF, tid);
    asm volatile("cp.async.commit_group;" ::: "memory");

    // ---- B fragments in registers, read directly from global W (one-time) ----
    float b0[4][16], b1[4][16];
    #pragma unroll
    for (int nt = 0; nt < 4; nt++) {
        int n = nc * 32 + nt * 8 + g;
        #pragma unroll
        for (int ks = 0; ks < 16; ks++) {
            b0[nt][ks] = tf32_rna(W[(ks * 8 + tig) * NF + n]);
            b1[nt][ks] = tf32_rna(W[(ks * 8 + tig + 4) * NF + n]);
        }
    }
    float bs0[4], bs1[4];
    #pragma unroll
    for (int nt = 0; nt < 4; nt++) {
        int col = nc * 32 + nt * 8 + 2 * tig;
        bs0[nt] = bias[col];
        bs1[nt] = bias[col + 1];
    }

    const int arow_in16 = lane & 15;     // row within m16 tile
    const int chunk_hi  = lane >> 4;     // 0/1: cols 0-3 vs 4-7

    int bi = 0;   // buffer holding tile t

    for (int t = t0; t < NTILES; t += GRID) {
        // prefetch tile t+2*GRID into buffer (bi+2)%3
        int tn = t + 2 * GRID;
        if (tn < NTILES) {
            int bn = bi + 2; if (bn >= NBUF) bn -= NBUF;
            load_tile(sbase + bn * SM_BUF_BYTES, x + (size_t)tn * TILE_M * NF, tid);
        }
        asm volatile("cp.async.commit_group;" ::: "memory");
        asm volatile("cp.async.wait_group 2;" ::: "memory");   // tile t resident
        __syncthreads();

        // ---- compute: warp tile 64(M) x 32(N), K=128 ----
        float acc[4][4][4];
        #pragma unroll
        for (int mt = 0; mt < 4; mt++)
            #pragma unroll
            for (int nt = 0; nt < 4; nt++) {
                acc[mt][nt][0] = 0.f; acc[mt][nt][1] = 0.f;
                acc[mt][nt][2] = 0.f; acc[mt][nt][3] = 0.f;
            }

        const uint32_t sbuf = sbase + bi * SM_BUF_BYTES;
        #pragma unroll
        for (int ks = 0; ks < 16; ks++) {
            uint32_t a[4][4];
            #pragma unroll
            for (int mt = 0; mt < 4; mt++) {
                int row   = mt * 16 + arow_in16;
                int chunk = 2 * ks + chunk_hi;
                uint32_t addr = sbuf + row * 512 + ((chunk ^ (row & 7)) << 4);
                ldm4(a[mt][0], a[mt][1], a[mt][2], a[mt][3], addr);
            }
            #pragma unroll
            for (int mt = 0; mt < 4; mt++)
                #pragma unroll
                for (int nt = 0; nt < 4; nt++)
                    mma_tf32(acc[mt][nt][0], acc[mt][nt][1], acc[mt][nt][2], acc[mt][nt][3],
                             a[mt][0], a[mt][1], a[mt][2], a[mt][3],
                             b0[nt][ks], b1[nt][ks]);
        }

        // ---- epilogue: bias add + streaming st.global.cs.v2 ----
        {
            const size_t rbase = (size_t)t * TILE_M;
            #pragma unroll
            for (int mt = 0; mt < 4; mt++) {
                int r = mt * 16 + g;
                #pragma unroll
                for (int nt = 0; nt < 4; nt++) {
                    int col = nc * 32 + nt * 8 + 2 * tig;
                    stg_cs_v2(out + (rbase + r) * NF + col,
                              acc[mt][nt][0] + bs0[nt], acc[mt][nt][1] + bs1[nt]);
                    stg_cs_v2(out + (rbase + r + 8) * NF + col,
                              acc[mt][nt][2] + bs0[nt], acc[mt][nt][3] + bs1[nt]);
                }
            }
        }
        __syncthreads();   // all warps done with buffer bi before it is re-filled
        bi = bi + 1; if (bi >= NBUF) bi -= NBUF;
    }
}

extern "C" void kernel_launch(void* const* d_in, const int* in_sizes, int n_in,
                              void* d_out, int out_size) {
    const float* x    = (const float*)d_in[0];
    const float* W    = (const float*)d_in[1];
    const float* bias = (const float*)d_in[2];
    float* out        = (float*)d_out;

    cudaFuncSetAttribute(gemm_kernel, cudaFuncAttributeMaxDynamicSharedMemorySize, SM_TOTAL);
    gemm_kernel<<<GRID, THREADS, SM_TOTAL>>>(x, W, bias, out);
}